// round 6
// baseline (speedup 1.0000x reference)
#include <cuda_runtime.h>
#include <cstdint>

#define NB 8
#define NN 1024
#define NC 1024
#define NH 16
#define HD 64
#define TOPK 256

// ---------------- scratch (static device globals; no allocation) ----------------
__device__ float g_qkv[(size_t)NB * NN * 3 * NC];     // 8192 x 3072
__device__ float g_attn[(size_t)NB * NH * NN * NN];   // 128 x 1024 x 1024
__device__ float g_x[(size_t)NB * NN * NC];
__device__ float g_y[(size_t)NB * NN * NC];
__device__ float g_sim[NB * NN];
__device__ float g_pooled[NB * NC];
__device__ float g_visinv[NB];
__device__ unsigned char g_mask[NB * NN];             // canonical 0/1 mask

// ---------------- mask canonicalization (auto-detect uint8 vs int32 bool) ----------------
__global__ __launch_bounds__(256) void mask_canon_kernel(const unsigned char* __restrict__ raw) {
    __shared__ int red[256];
    int tid = threadIdx.x;
    // If the mask is int32 (bool upcast), every byte at position p%4!=0 is zero.
    // If uint8, ~3/8 of all bytes at p%4!=0 are 1. Detect by OR-reduction.
    int any = 0;
    for (int i = tid; i < NB * NN; i += 256)
        if ((i & 3) != 0 && raw[i] != 0) any = 1;
    red[tid] = any;
    __syncthreads();
#pragma unroll
    for (int off = 128; off > 0; off >>= 1) {
        if (tid < off) red[tid] |= red[tid + off];
        __syncthreads();
    }
    int is_u8 = red[0];
    const int* raw32 = (const int*)raw;
    for (int i = tid; i < NB * NN; i += 256) {
        unsigned char v = is_u8 ? (raw[i] != 0) : (raw32[i] != 0);
        g_mask[i] = v;
    }
}

// ---------------- helpers ----------------
__device__ __forceinline__ unsigned fkey(float f) {
    unsigned u = __float_as_uint(f);
    return (u & 0x80000000u) ? ~u : (u | 0x80000000u);  // monotone: bigger float -> bigger key
}

__device__ __forceinline__ float blk_reduce_sum(float v, float* red) {
    int tid = threadIdx.x;
    red[tid] = v;
    __syncthreads();
#pragma unroll
    for (int off = 128; off > 0; off >>= 1) {
        if (tid < off) red[tid] += red[tid + off];
        __syncthreads();
    }
    float r = red[0];
    __syncthreads();
    return r;
}

__device__ __forceinline__ float blk_reduce_max(float v, float* red) {
    int tid = threadIdx.x;
    red[tid] = v;
    __syncthreads();
#pragma unroll
    for (int off = 128; off > 0; off >>= 1) {
        if (tid < off) red[tid] = fmaxf(red[tid], red[tid + off]);
        __syncthreads();
    }
    float r = red[0];
    __syncthreads();
    return r;
}

// Exact descending radix select over 1024 keys in smem (256 threads).
// On return: sel[0] = threshold key t (the kwant-th largest),
//            sel[1] = rem = number of (key == t) elements that belong in the top-kwant.
__device__ __forceinline__ void radix_select_1024(const unsigned* sk, unsigned kwant,
                                                  unsigned* hist, unsigned* ss,
                                                  unsigned* sel, int tid) {
    if (tid == 0) { sel[0] = 0u; sel[1] = kwant; }
    unsigned pmask = 0u;
    __syncthreads();
    for (int shift = 24; shift >= 0; shift -= 8) {
        hist[tid] = 0u;
        __syncthreads();
        unsigned prefix = sel[0];
#pragma unroll
        for (int i = 0; i < 4; i++) {
            unsigned k = sk[tid + i * 256];
            if ((k & pmask) == prefix) atomicAdd(&hist[(k >> shift) & 255], 1u);
        }
        __syncthreads();
        ss[tid] = hist[tid];
        __syncthreads();
#pragma unroll
        for (int off = 1; off < 256; off <<= 1) {   // suffix (descending) inclusive scan
            unsigned v = (tid + off < 256) ? ss[tid + off] : 0u;
            __syncthreads();
            ss[tid] += v;
            __syncthreads();
        }
        unsigned rem = sel[1];
        unsigned h = hist[tid];
        unsigned above = (tid < 255) ? ss[tid + 1] : 0u;
        __syncthreads();  // everyone has read rem/prefix before the winner writes
        if (above < rem && above + h >= rem) {
            sel[0] = prefix | ((unsigned)tid << shift);
            sel[1] = rem - above;
        }
        pmask |= (0xFFu << shift);
        __syncthreads();
    }
}

// ---------------- generic fp32 GEMM: C = A(MxK) * B(KxN) + bias (+ residual) ----------------
// BM=128 BN=128 BK=16, 256 threads, 8x8 per thread.
__global__ __launch_bounds__(256) void gemm_kernel(const float* __restrict__ A,
                                                   const float* __restrict__ B,
                                                   const float* __restrict__ bias,
                                                   const float* __restrict__ res,
                                                   float* __restrict__ C,
                                                   int M, int N, int K) {
    __shared__ float As[16][132];  // [k][m]
    __shared__ float Bs[16][132];  // [k][n]
    int tid = threadIdx.x;
    int m0 = blockIdx.y * 128, n0 = blockIdx.x * 128;
    int ty = tid >> 4, tx = tid & 15;
    float acc[8][8];
#pragma unroll
    for (int r = 0; r < 8; r++)
#pragma unroll
        for (int c = 0; c < 8; c++) acc[r][c] = 0.f;

    for (int k0 = 0; k0 < K; k0 += 16) {
#pragma unroll
        for (int i = 0; i < 2; i++) {  // A tile: 128x16 as 512 float4
            int lin = tid + i * 256;
            int m = lin >> 2;
            int kq = (lin & 3) << 2;
            float4 v = *(const float4*)(A + (size_t)(m0 + m) * K + k0 + kq);
            As[kq + 0][m] = v.x; As[kq + 1][m] = v.y;
            As[kq + 2][m] = v.z; As[kq + 3][m] = v.w;
        }
#pragma unroll
        for (int i = 0; i < 2; i++) {  // B tile: 16x128
            int lin = tid + i * 256;
            int k = lin >> 5;
            int nq = (lin & 31) << 2;
            *(float4*)(&Bs[k][nq]) = *(const float4*)(B + (size_t)(k0 + k) * N + n0 + nq);
        }
        __syncthreads();
#pragma unroll
        for (int k = 0; k < 16; k++) {
            float a[8], bb[8];
            *(float4*)&a[0] = *(float4*)&As[k][ty * 8];
            *(float4*)&a[4] = *(float4*)&As[k][ty * 8 + 4];
            *(float4*)&bb[0] = *(float4*)&Bs[k][tx * 8];
            *(float4*)&bb[4] = *(float4*)&Bs[k][tx * 8 + 4];
#pragma unroll
            for (int r = 0; r < 8; r++)
#pragma unroll
                for (int c = 0; c < 8; c++) acc[r][c] += a[r] * bb[c];
        }
        __syncthreads();
    }
#pragma unroll
    for (int r = 0; r < 8; r++) {
        int m = m0 + ty * 8 + r;
#pragma unroll
        for (int c = 0; c < 8; c += 4) {
            int n = n0 + tx * 8 + c;
            float4 v;
            v.x = acc[r][c + 0] + bias[n + 0];
            v.y = acc[r][c + 1] + bias[n + 1];
            v.z = acc[r][c + 2] + bias[n + 2];
            v.w = acc[r][c + 3] + bias[n + 3];
            if (res) {
                float4 rr = *(const float4*)(res + (size_t)m * N + n);
                v.x += rr.x; v.y += rr.y; v.z += rr.z; v.w += rr.w;
            }
            *(float4*)(C + (size_t)m * N + n) = v;
        }
    }
}

// ---------------- attn scores: per (b,h): Q(1024x64) K^T -> attn ----------------
__global__ __launch_bounds__(256) void attn_gemm_kernel(const float* __restrict__ qkv,
                                                        float* __restrict__ attn) {
    __shared__ float Qs[64][68];  // [d][q]
    __shared__ float Ks[64][68];  // [d][k]
    int tid = threadIdx.x;
    int q0 = blockIdx.x * 64, k0 = blockIdx.y * 64;
    int bh = blockIdx.z;
    int b = bh >> 4, h = bh & 15;
    size_t qbase = ((size_t)b * NN + q0) * 3072 + h * 64;
    size_t kbase = ((size_t)b * NN + k0) * 3072 + 1024 + h * 64;
    int r = tid >> 4;
    int d4 = (tid & 15) << 2;
#pragma unroll
    for (int i = 0; i < 4; i++) {
        int row = r + i * 16;
        float4 qv = *(const float4*)(qkv + qbase + (size_t)row * 3072 + d4);
        Qs[d4 + 0][row] = qv.x; Qs[d4 + 1][row] = qv.y;
        Qs[d4 + 2][row] = qv.z; Qs[d4 + 3][row] = qv.w;
        float4 kv = *(const float4*)(qkv + kbase + (size_t)row * 3072 + d4);
        Ks[d4 + 0][row] = kv.x; Ks[d4 + 1][row] = kv.y;
        Ks[d4 + 2][row] = kv.z; Ks[d4 + 3][row] = kv.w;
    }
    __syncthreads();
    int qr = (tid >> 4) << 2;
    int kc = (tid & 15) << 2;
    float acc[4][4];
#pragma unroll
    for (int r2 = 0; r2 < 4; r2++)
#pragma unroll
        for (int c = 0; c < 4; c++) acc[r2][c] = 0.f;
#pragma unroll
    for (int d = 0; d < 64; d++) {
        float a[4], bb[4];
        *(float4*)a = *(float4*)&Qs[d][qr];
        *(float4*)bb = *(float4*)&Ks[d][kc];
#pragma unroll
        for (int r2 = 0; r2 < 4; r2++)
#pragma unroll
            for (int c = 0; c < 4; c++) acc[r2][c] += a[r2] * bb[c];
    }
    const float scale = 0.125f;  // 64^-0.5
#pragma unroll
    for (int r2 = 0; r2 < 4; r2++) {
        float4 v;
        v.x = acc[r2][0] * scale; v.y = acc[r2][1] * scale;
        v.z = acc[r2][2] * scale; v.w = acc[r2][3] * scale;
        *(float4*)(attn + ((size_t)bh * NN + q0 + qr + r2) * NN + k0 + kc) = v;
    }
}

// ---------------- per-row top-256 + double softmax, in-place on attn ----------------
__global__ __launch_bounds__(256) void topk_softmax_kernel(float* __restrict__ attn) {
    int row = blockIdx.x;            // (b*16+h)*1024 + q
    int b = row >> 14;
    int tid = threadIdx.x;
    float* a = attn + (size_t)row * NN;
    __shared__ float sv[1024];
    __shared__ unsigned sk[1024];
    __shared__ unsigned hist[256];
    __shared__ unsigned ss[256];
    __shared__ float red[256];
    __shared__ unsigned sel[2];
    __shared__ unsigned char tieflag[1024];
    __shared__ int s_partial;

    float lm = -3.4e38f;
#pragma unroll
    for (int i = 0; i < 4; i++) {
        int idx = tid + i * 256;
        float v = a[idx];
        sv[idx] = v;
        sk[idx] = fkey(v);
        lm = fmaxf(lm, v);
    }
    __syncthreads();
    float m = blk_reduce_max(lm, red);

    radix_select_1024(sk, TOPK, hist, ss, sel, tid);
    unsigned tk = sel[0];
    unsigned rem = sel[1];

    if (tid == 0) hist[0] = 0;
    __syncthreads();
#pragma unroll
    for (int i = 0; i < 4; i++)
        if (sk[tid + i * 256] == tk) atomicAdd(&hist[0], 1u);
    __syncthreads();
    unsigned cnt_eq = hist[0];
    if (tid == 0) {
        s_partial = (rem < cnt_eq);
        if (rem < cnt_eq) {  // rare: partial ties, take lowest indices (jax tie-break)
            unsigned taken = 0;
            for (int k = 0; k < 1024; k++) {
                unsigned char f = (sk[k] == tk && taken < rem) ? 1 : 0;
                tieflag[k] = f;
                taken += f;
            }
        }
    }
    __syncthreads();
    int partial = s_partial;

    float lS = 0.f;
#pragma unroll
    for (int i = 0; i < 4; i++) {
        int idx = tid + i * 256;
        unsigned k = sk[idx];
        bool inc = (k > tk) || (k == tk && (!partial || tieflag[idx]));
        if (inc) lS += __expf(sv[idx] - m);
    }
    float S = blk_reduce_sum(lS, red);
    float invS = 1.f / S;

    float lz = 0.f;
#pragma unroll
    for (int i = 0; i < 4; i++) {
        int idx = tid + i * 256;
        float e;
        if (g_mask[b * NN + idx]) {
            e = 0.f;                                   // masked -> -inf -> exp = 0
        } else {
            unsigned k = sk[idx];
            bool inc = (k > tk) || (k == tk && (!partial || tieflag[idx]));
            e = inc ? __expf(__expf(sv[idx] - m) * invS) : 1.f;  // exp(p) or exp(0)
        }
        sv[idx] = e;
        lz += e;
    }
    float Z = blk_reduce_sum(lz, red);
    float invZ = 1.f / Z;
#pragma unroll
    for (int i = 0; i < 4; i++) {
        int idx = tid + i * 256;
        a[idx] = sv[idx] * invZ;
    }
}

// ---------------- AV: per (b,h): attn_w(1024x1024) @ V(1024x64) -> x (B,N,C) ----------------
__global__ __launch_bounds__(256) void av_gemm_kernel(const float* __restrict__ attn,
                                                      const float* __restrict__ qkv,
                                                      float* __restrict__ x) {
    __shared__ float Ws[64][68];  // [kk][q]
    __shared__ float Vs[64][68];  // [kk][d]
    int tid = threadIdx.x;
    int q0 = blockIdx.x * 64;
    int bh = blockIdx.y;
    int b = bh >> 4, h = bh & 15;
    int r = tid >> 4;
    int c4 = (tid & 15) << 2;
    int qr = (tid >> 4) << 2;
    int dc = (tid & 15) << 2;
    float acc[4][4];
#pragma unroll
    for (int r2 = 0; r2 < 4; r2++)
#pragma unroll
        for (int c = 0; c < 4; c++) acc[r2][c] = 0.f;

    for (int kt = 0; kt < NN; kt += 64) {
#pragma unroll
        for (int i = 0; i < 4; i++) {
            int row = r + i * 16;
            float4 w = *(const float4*)(attn + ((size_t)bh * NN + q0 + row) * NN + kt + c4);
            Ws[c4 + 0][row] = w.x; Ws[c4 + 1][row] = w.y;
            Ws[c4 + 2][row] = w.z; Ws[c4 + 3][row] = w.w;
            float4 vv = *(const float4*)(qkv + ((size_t)b * NN + kt + row) * 3072 + 2048 + h * 64 + c4);
            *(float4*)&Vs[row][c4] = vv;
        }
        __syncthreads();
#pragma unroll
        for (int kk = 0; kk < 64; kk++) {
            float a[4], bb[4];
            *(float4*)a = *(float4*)&Ws[kk][qr];
            *(float4*)bb = *(float4*)&Vs[kk][dc];
#pragma unroll
            for (int r2 = 0; r2 < 4; r2++)
#pragma unroll
                for (int c = 0; c < 4; c++) acc[r2][c] += a[r2] * bb[c];
        }
        __syncthreads();
    }
#pragma unroll
    for (int r2 = 0; r2 < 4; r2++) {
        float4 v;
        v.x = acc[r2][0]; v.y = acc[r2][1]; v.z = acc[r2][2]; v.w = acc[r2][3];
        *(float4*)(x + ((size_t)b * NN + q0 + qr + r2) * NC + h * 64 + dc) = v;
    }
}

// ---------------- row layernorm over 1024 ----------------
__global__ __launch_bounds__(256) void ln_kernel(const float* __restrict__ in,
                                                 const float* __restrict__ g,
                                                 const float* __restrict__ bt,
                                                 float* __restrict__ out) {
    int row = blockIdx.x, tid = threadIdx.x;
    __shared__ float xs[1024];
    __shared__ float red[256];
    const float* p = in + (size_t)row * 1024;
    float s = 0.f;
#pragma unroll
    for (int i = 0; i < 4; i++) {
        float v = p[tid + i * 256];
        xs[tid + i * 256] = v;
        s += v;
    }
    float mu = blk_reduce_sum(s, red) * (1.f / 1024.f);
    float vs = 0.f;
#pragma unroll
    for (int i = 0; i < 4; i++) {
        float d = xs[tid + i * 256] - mu;
        vs += d * d;
    }
    float var = blk_reduce_sum(vs, red) * (1.f / 1024.f);
    float rstd = rsqrtf(var + 1e-5f);
#pragma unroll
    for (int i = 0; i < 4; i++) {
        int idx = tid + i * 256;
        out[(size_t)row * 1024 + idx] = (xs[idx] - mu) * rstd * g[idx] + bt[idx];
    }
}

// ---------------- vis token inverse norms ----------------
__global__ __launch_bounds__(256) void visnorm_kernel(const float* __restrict__ vis,
                                                      float* __restrict__ visinv) {
    int b = blockIdx.x, tid = threadIdx.x;
    __shared__ float red[256];
    float s = 0.f;
#pragma unroll
    for (int i = 0; i < 4; i++) {
        float v = vis[b * 1024 + tid + i * 256];
        s += v * v;
    }
    float t = blk_reduce_sum(s, red);
    if (tid == 0) visinv[b] = 1.f / fmaxf(sqrtf(t), 1e-12f);
}

// ---------------- sim = sigmoid(beta + alpha * dot(vis_n, tf_n)), masked -> 0 ----------------
__global__ __launch_bounds__(256) void sim_kernel(const float* __restrict__ vis,
                                                  const float* __restrict__ tf,
                                                  const float* __restrict__ alpha,
                                                  const float* __restrict__ beta,
                                                  const float* __restrict__ visinv,
                                                  float* __restrict__ sim) {
    int bn = blockIdx.x;  // b*1024 + n
    int b = bn >> 10;
    int tid = threadIdx.x;
    __shared__ float red[256];
    __shared__ float ts[1024];
    const float* vrow = vis + b * 1024;
    const float* trow = tf + (size_t)bn * 1024;
    float q = 0.f;
#pragma unroll
    for (int i = 0; i < 4; i++) {
        int idx = tid + i * 256;
        float tv = trow[idx];
        ts[idx] = tv;
        q += tv * tv;
    }
    q = blk_reduce_sum(q, red);
    float invt = 1.f / fmaxf(sqrtf(q), 1e-12f);
    float vi = visinv[b];
    // normalize-then-dot, exact fp32 (matches reference l2norm -> einsum)
    float d = 0.f;
#pragma unroll
    for (int i = 0; i < 4; i++) {
        int idx = tid + i * 256;
        d += (vrow[idx] * vi) * (ts[idx] * invt);
    }
    d = blk_reduce_sum(d, red);
    if (tid == 0) {
        float s;
        if (g_mask[bn]) {
            s = 0.f;  // sigmoid(-inf)
        } else {
            float val = beta[0] + alpha[0] * d;
            s = 1.f / (1.f + __expf(-val));
        }
        sim[bn] = s;
    }
}

// ---------------- top-256 sim pooling + txt_token add ----------------
__global__ __launch_bounds__(256) void pool_kernel(const float* __restrict__ sim,
                                                   const float* __restrict__ tf,
                                                   const float* __restrict__ txt,
                                                   float* __restrict__ pooled) {
    int b = blockIdx.x, tid = threadIdx.x;
    __shared__ unsigned sk[1024];
    __shared__ unsigned hist[256];
    __shared__ unsigned ss[256];
    __shared__ unsigned sel[2];
    __shared__ unsigned char tieflag[1024];
    __shared__ int s_partial;
    __shared__ unsigned sc[256];
    __shared__ short list[256];
#pragma unroll
    for (int i = 0; i < 4; i++) {
        int idx = tid + i * 256;
        sk[idx] = fkey(sim[b * 1024 + idx]);
    }
    __syncthreads();
    radix_select_1024(sk, TOPK, hist, ss, sel, tid);
    unsigned tk = sel[0];
    unsigned rem = sel[1];
    if (tid == 0) hist[0] = 0;
    __syncthreads();
#pragma unroll
    for (int i = 0; i < 4; i++)
        if (sk[tid + i * 256] == tk) atomicAdd(&hist[0], 1u);
    __syncthreads();
    unsigned cnt_eq = hist[0];
    if (tid == 0) {
        s_partial = (rem < cnt_eq);
        if (rem < cnt_eq) {  // ties: lowest indices win (jax top_k tie-break)
            unsigned taken = 0;
            for (int k = 0; k < 1024; k++) {
                unsigned char f = (sk[k] == tk && taken < rem) ? 1 : 0;
                tieflag[k] = f;
                taken += f;
            }
        }
    }
    __syncthreads();
    int partial = s_partial;

    // compact included indices (exactly 256) preserving index order
    int base = tid * 4;
    unsigned cnt = 0;
    unsigned char f[4];
#pragma unroll
    for (int j = 0; j < 4; j++) {
        int k = base + j;
        unsigned kk = sk[k];
        bool inc = (kk > tk) || (kk == tk && (!partial || tieflag[k]));
        f[j] = inc;
        cnt += inc;
    }
    sc[tid] = cnt;
    __syncthreads();
#pragma unroll
    for (int off = 1; off < 256; off <<= 1) {
        unsigned v = (tid >= off) ? sc[tid - off] : 0u;
        __syncthreads();
        sc[tid] += v;
        __syncthreads();
    }
    unsigned pos = sc[tid] - cnt;
#pragma unroll
    for (int j = 0; j < 4; j++)
        if (f[j]) list[pos++] = (short)(base + j);
    __syncthreads();

    float acc[4] = {0.f, 0.f, 0.f, 0.f};
    for (int j = 0; j < TOPK; j++) {
        int n = list[j];
        const float* rrow = tf + ((size_t)b * 1024 + n) * 1024;
#pragma unroll
        for (int i = 0; i < 4; i++) acc[i] += rrow[tid + i * 256];
    }
#pragma unroll
    for (int i = 0; i < 4; i++) {
        int c = tid + i * 256;
        pooled[b * 1024 + c] = acc[i] * (1.f / 256.f) + txt[b * 1024 + c];
    }
}

// ---------------- tt = LN(pooled @ Wp1 + bp1) ----------------
__global__ __launch_bounds__(256) void final_kernel(const float* __restrict__ pooled,
                                                    const float* __restrict__ W,
                                                    const float* __restrict__ bias,
                                                    const float* __restrict__ g,
                                                    const float* __restrict__ bt,
                                                    float* __restrict__ out) {
    int b = blockIdx.x, tid = threadIdx.x;
    __shared__ float ts[1024];
    __shared__ float ys[1024];
    __shared__ float red[256];
#pragma unroll
    for (int i = 0; i < 4; i++) ts[tid + i * 256] = pooled[b * 1024 + tid + i * 256];
    __syncthreads();
    float acc[4] = {0.f, 0.f, 0.f, 0.f};
#pragma unroll 4
    for (int c = 0; c < 1024; c++) {
        float tc = ts[c];
        const float* wr = W + (size_t)c * 1024 + tid;
        acc[0] += tc * wr[0];
        acc[1] += tc * wr[256];
        acc[2] += tc * wr[512];
        acc[3] += tc * wr[768];
    }
    float s = 0.f;
#pragma unroll
    for (int i = 0; i < 4; i++) {
        float y = acc[i] + bias[tid + i * 256];
        ys[tid + i * 256] = y;
        s += y;
    }
    float mu = blk_reduce_sum(s, red) * (1.f / 1024.f);
    float vs = 0.f;
#pragma unroll
    for (int i = 0; i < 4; i++) {
        float d = ys[tid + i * 256] - mu;
        vs += d * d;
    }
    float var = blk_reduce_sum(vs, red) * (1.f / 1024.f);
    float rstd = rsqrtf(var + 1e-5f);
#pragma unroll
    for (int i = 0; i < 4; i++) {
        int idx = tid + i * 256;
        out[b * 1024 + idx] = (ys[idx] - mu) * rstd * g[idx] + bt[idx];
    }
}

// ---------------- host launch ----------------
extern "C" void kernel_launch(void* const* d_in, const int* in_sizes, int n_in,
                              void* d_out, int out_size) {
    const float* txt_token = (const float*)d_in[0];
    const float* text_features = (const float*)d_in[1];
    const unsigned char* text_mask = (const unsigned char*)d_in[2];
    const float* vis_token = (const float*)d_in[3];
    // top_lens may or may not appear as a scalar input at index 4
    int o = (n_in > 4 && in_sizes[4] == 1) ? 1 : 0;
    const float* Wqkv = (const float*)d_in[4 + o];
    const float* bqkv = (const float*)d_in[5 + o];
    const float* Wp2 = (const float*)d_in[6 + o];
    const float* bp2 = (const float*)d_in[7 + o];
    const float* ln2_g = (const float*)d_in[8 + o];
    const float* ln2_b = (const float*)d_in[9 + o];
    const float* sim_alpha = (const float*)d_in[10 + o];
    const float* sim_beta = (const float*)d_in[11 + o];
    const float* Wp1 = (const float*)d_in[12 + o];
    const float* bp1 = (const float*)d_in[13 + o];
    const float* ln1_g = (const float*)d_in[14 + o];
    const float* ln1_b = (const float*)d_in[15 + o];

    float* out = (float*)d_out;
    float* tt = out;                 // (8,1,1024)
    float* tf = out + NB * NC;       // (8,1024,1024)

    float *qkv, *attn, *x, *y, *simv, *pooled, *visinv;
    cudaGetSymbolAddress((void**)&qkv, g_qkv);
    cudaGetSymbolAddress((void**)&attn, g_attn);
    cudaGetSymbolAddress((void**)&x, g_x);
    cudaGetSymbolAddress((void**)&y, g_y);
    cudaGetSymbolAddress((void**)&simv, g_sim);
    cudaGetSymbolAddress((void**)&pooled, g_pooled);
    cudaGetSymbolAddress((void**)&visinv, g_visinv);

    // 0. canonicalize mask (auto-detect uint8 vs int32 bool layout)
    mask_canon_kernel<<<1, 256>>>(text_mask);
    // 1. qkv = X @ Wqkv + bqkv
    gemm_kernel<<<dim3(3072 / 128, 8192 / 128), 256>>>(text_features, Wqkv, bqkv, nullptr,
                                                       qkv, 8192, 3072, 1024);
    // 2. attn = Q K^T * scale
    attn_gemm_kernel<<<dim3(16, 16, 128), 256>>>(qkv, attn);
    // 3. top-256 + double softmax (in place)
    topk_softmax_kernel<<<NB * NH * NN, 256>>>(attn);
    // 4. x = attn_w @ V  (layout B,N,C)
    av_gemm_kernel<<<dim3(16, 128), 256>>>(attn, qkv, x);
    // 5. y = x @ Wp2 + bp2 + text_features
    gemm_kernel<<<dim3(1024 / 128, 8192 / 128), 256>>>(x, Wp2, bp2, text_features,
                                                       y, 8192, 1024, 1024);
    // 6. tf = layernorm(y)
    ln_kernel<<<8192, 256>>>(y, ln2_g, ln2_b, tf);
    // 7-8. sim
    visnorm_kernel<<<NB, 256>>>(vis_token, visinv);
    sim_kernel<<<NB * NN, 256>>>(vis_token, tf, sim_alpha, sim_beta, visinv, simv);
    // 9. pooled (+ txt_token)
    pool_kernel<<<NB, 256>>>(simv, tf, txt_token, pooled);
    // 10. tt = LN(pooled @ Wp1 + bp1)
    final_kernel<<<NB, 256>>>(pooled, Wp1, bp1, ln1_g, ln1_b, tt);
    (void)out_size;
}